// round 1
// baseline (speedup 1.0000x reference)
#include <cuda_runtime.h>

#define NN  100000
#define EE  1600000
#define PP  800000
#define HEN 20000
#define FIN 128
#define D   64
#define NC  40

// ---------------- scratch (device globals; no allocation allowed) ----------------
__device__ float g_xw [NN * D];     // gemm output / xwd
__device__ float g_acc[NN * D];     // scatter accumulator (also reused at width 40)
__device__ float g_h1 [NN * D];     // hyperconv1 output (relu'd)
__device__ float g_h2 [NN * D];     // hyperconv2 output
__device__ float g_xg [NN * D];     // gcn1 output (relu'd)
__device__ float g_t40[NN * NC];    // gcn2 pre-scatter (xwd, width 40)
__device__ float g_ef [HEN * D];    // hyperedge features
__device__ float g_Dn [NN];         // hypergraph node degree
__device__ float g_Bh [HEN];        // hyperedge size
__device__ float g_dis[NN];         // gcn: rsqrt(deg+1)  (also deg accumulator)
__device__ int   g_me, g_mh;        // 1 if int64 indices, 0 if int32

// ---------------- helpers ----------------
__device__ __forceinline__ long long ldidx(const void* b, long long i, int m64) {
    return m64 ? ((const long long*)b)[i] : (long long)((const int*)b)[i];
}

__device__ __forceinline__ void red4(float* p, float4 v) {
    asm volatile("red.global.add.v4.f32 [%0], {%1, %2, %3, %4};"
                 :: "l"(p), "f"(v.x), "f"(v.y), "f"(v.z), "f"(v.w) : "memory");
}

// ---------------- dtype detection ----------------
// If indices are stored as int64 (values < 2^31), every odd int32 word is 0.
__global__ void k_detect(const int* e32, const int* h32) {
    int nze = 0, nzh = 0;
    for (int i = threadIdx.x; i < 4096; i += blockDim.x) {
        if (e32[2 * i + 1] != 0) nze = 1;
        if (h32[2 * i + 1] != 0) nzh = 1;
    }
    nze = __syncthreads_or(nze);
    nzh = __syncthreads_or(nzh);
    if (threadIdx.x == 0) { g_me = nze ? 0 : 1; g_mh = nzh ? 0 : 1; }
}

// ---------------- zeroing ----------------
__global__ void k_zero_deg() {
    int i = blockIdx.x * blockDim.x + threadIdx.x;
    if (i < NN) { g_Dn[i] = 0.f; g_dis[i] = 0.f; }
    if (i < HEN) g_Bh[i] = 0.f;
}
__global__ void k_zero_ef() {
    int i = blockIdx.x * blockDim.x + threadIdx.x;
    if (i < HEN * D) g_ef[i] = 0.f;
}
__global__ void k_zero_acc64() {
    int i = blockIdx.x * blockDim.x + threadIdx.x;
    if (i < NN * D) g_acc[i] = 0.f;
}
__global__ void k_zero_acc40() {
    int i = blockIdx.x * blockDim.x + threadIdx.x;
    if (i < NN * NC) g_acc[i] = 0.f;
}

// ---------------- degrees ----------------
__global__ void k_hdeg(const void* hidx) {
    int i = blockIdx.x * blockDim.x + threadIdx.x;
    if (i >= PP) return;
    int m = g_mh;
    int node = (int)ldidx(hidx, i, m);
    int he   = (int)ldidx(hidx, (long long)PP + i, m);
    atomicAdd(&g_Dn[node], 1.f);
    atomicAdd(&g_Bh[he], 1.f);
}
__global__ void k_gdeg(const void* eidx) {
    int i = blockIdx.x * blockDim.x + threadIdx.x;
    if (i >= EE) return;
    int dst = (int)ldidx(eidx, (long long)EE + i, g_me);
    atomicAdd(&g_dis[dst], 1.f);
}
__global__ void k_fin_dis() {
    int i = blockIdx.x * blockDim.x + threadIdx.x;
    if (i < NN) g_dis[i] = rsqrtf(g_dis[i] + 1.0f);  // +1 self loop; always > 0
}

// ---------------- GEMMs (W resident in shared; uniform row broadcast loads) ----------------
template<int K, int C>
__global__ void k_gemm(const float* __restrict__ A, const float* __restrict__ W,
                       float* __restrict__ out, const float* __restrict__ rowscale) {
    __shared__ float Ws[K * C];
    int tid = threadIdx.y * C + threadIdx.x;
    int nth = blockDim.x * blockDim.y;
    for (int i = tid; i < K * C; i += nth) Ws[i] = W[i];
    __syncthreads();
    int tx = threadIdx.x;
    int r0 = blockIdx.x * (blockDim.y * 8) + threadIdx.y * 8;
    for (int rr = 0; rr < 8; rr++) {
        int r = r0 + rr;
        if (r >= NN) return;
        const float* a = A + (size_t)r * K;
        float s = 0.f;
        #pragma unroll 16
        for (int k = 0; k < K; k++) s = fmaf(__ldg(a + k), Ws[k * C + tx], s);
        if (rowscale) s *= rowscale[r];
        out[(size_t)r * C + tx] = s;
    }
}

// concat GEMM: [x | h2] @ W_c1  (K = 128 + 64), prescaled by dis
__global__ void k_gemm_cat(const float* __restrict__ A1, const float* __restrict__ A2,
                           const float* __restrict__ W, float* __restrict__ out,
                           const float* __restrict__ rowscale) {
    __shared__ float Ws[(FIN + D) * D];   // 192*64*4 = 48KB
    int tid = threadIdx.y * D + threadIdx.x;
    for (int i = tid; i < (FIN + D) * D; i += 256) Ws[i] = W[i];
    __syncthreads();
    int tx = threadIdx.x;
    int r0 = blockIdx.x * 32 + threadIdx.y * 8;
    for (int rr = 0; rr < 8; rr++) {
        int r = r0 + rr;
        if (r >= NN) return;
        const float* a1 = A1 + (size_t)r * FIN;
        const float* a2 = A2 + (size_t)r * D;
        float s = 0.f;
        #pragma unroll 16
        for (int k = 0; k < FIN; k++) s = fmaf(__ldg(a1 + k), Ws[k * D + tx], s);
        #pragma unroll 16
        for (int k = 0; k < D; k++)   s = fmaf(__ldg(a2 + k), Ws[(FIN + k) * D + tx], s);
        s *= rowscale[r];
        out[(size_t)r * D + tx] = s;
    }
}

// ---------------- hypergraph scatters ----------------
__global__ void k_scat_n2e(const float* __restrict__ xw, const void* hidx) {
    long long t = (long long)blockIdx.x * blockDim.x + threadIdx.x;
    int pair = (int)(t >> 4), lane = (int)(t & 15);
    if (pair >= PP) return;
    int m = g_mh;
    int node = (int)ldidx(hidx, pair, m);
    int he   = (int)ldidx(hidx, (long long)PP + pair, m);
    float4 v = *(const float4*)(xw + (size_t)node * D + lane * 4);
    red4(g_ef + (size_t)he * D + lane * 4, v);
}
__global__ void k_scale_ef() {
    int i = blockIdx.x * blockDim.x + threadIdx.x;
    if (i >= HEN * D) return;
    float b = g_Bh[i >> 6];
    g_ef[i] *= (b > 0.f) ? (1.f / b) : 0.f;
}
__global__ void k_scat_e2n(const void* hidx) {
    long long t = (long long)blockIdx.x * blockDim.x + threadIdx.x;
    int pair = (int)(t >> 4), lane = (int)(t & 15);
    if (pair >= PP) return;
    int m = g_mh;
    int node = (int)ldidx(hidx, pair, m);
    int he   = (int)ldidx(hidx, (long long)PP + pair, m);
    float4 v = *(const float4*)(g_ef + (size_t)he * D + lane * 4);
    red4(g_acc + (size_t)node * D + lane * 4, v);
}
__global__ void k_epi_hyper(const float* __restrict__ bias, float* __restrict__ out, int do_relu) {
    int i = blockIdx.x * blockDim.x + threadIdx.x;
    if (i >= NN * D) return;
    int n = i >> 6, c = i & 63;
    float d = g_Dn[n];
    float dinv = (d > 0.f) ? (1.f / d) : 0.f;
    float v = dinv * g_acc[i] + bias[c];
    if (do_relu) v = fmaxf(v, 0.f);
    out[i] = v;
}

// ---------------- GCN scatters ----------------
__global__ void k_gcn_scat64(const float* __restrict__ xwd, const void* eidx) {
    long long t = (long long)blockIdx.x * blockDim.x + threadIdx.x;
    int e = (int)(t >> 4), lane = (int)(t & 15);
    if (e >= EE) return;
    int m = g_me;
    int src = (int)ldidx(eidx, e, m);
    int dst = (int)ldidx(eidx, (long long)EE + e, m);
    float4 v = *(const float4*)(xwd + (size_t)src * D + lane * 4);
    red4(g_acc + (size_t)dst * D + lane * 4, v);
}
__global__ void k_epi_gcn(const float* __restrict__ xwd, const float* __restrict__ bias,
                          float* __restrict__ out) {
    int i = blockIdx.x * blockDim.x + threadIdx.x;
    if (i >= NN * D) return;
    int n = i >> 6, c = i & 63;
    float v = g_dis[n] * (g_acc[i] + xwd[i]) + bias[c];
    out[i] = fmaxf(v, 0.f);
}
__global__ void k_gcn_scat40(const void* eidx) {
    int tid = threadIdx.x;                 // blockDim = 320 -> 32 edges/block
    int e = blockIdx.x * 32 + tid / 10;
    int lane = tid % 10;
    if (e >= EE) return;
    int m = g_me;
    int src = (int)ldidx(eidx, e, m);
    int dst = (int)ldidx(eidx, (long long)EE + e, m);
    float4 v = *(const float4*)(g_t40 + (size_t)src * NC + lane * 4);
    red4(g_acc + (size_t)dst * NC + lane * 4, v);
}

// ---------------- final: gcn2 epilogue fused with @W_lp + b_lp ----------------
__global__ void k_final(const float* __restrict__ Wlp, const float* __restrict__ blp,
                        const float* __restrict__ bc2, float* __restrict__ out) {
    __shared__ float Ws[NC * NC];
    __shared__ float vs[6][NC];
    int tid = threadIdx.x;                 // 240 threads = 6 nodes x 40
    for (int i = tid; i < NC * NC; i += 240) Ws[i] = Wlp[i];
    int ln = tid / NC, c = tid % NC;
    int n = blockIdx.x * 6 + ln;
    __syncthreads();
    if (n < NN) {
        float dis = g_dis[n];
        vs[ln][c] = dis * (g_acc[(size_t)n * NC + c] + g_t40[(size_t)n * NC + c]) + bc2[c];
    }
    __syncthreads();
    if (n < NN) {
        float s = blp[c];
        #pragma unroll
        for (int k = 0; k < NC; k++) s = fmaf(vs[ln][k], Ws[k * NC + c], s);
        out[(size_t)n * NC + c] = s;
    }
}

// ---------------- launch ----------------
extern "C" void kernel_launch(void* const* d_in, const int* in_sizes, int n_in,
                              void* d_out, int out_size) {
    const float* x    = (const float*)d_in[0];
    const void*  eidx = d_in[1];
    const void*  hidx = d_in[2];
    const float* W_h1 = (const float*)d_in[3];
    const float* b_h1 = (const float*)d_in[4];
    const float* W_h2 = (const float*)d_in[5];
    const float* b_h2 = (const float*)d_in[6];
    const float* W_c1 = (const float*)d_in[7];
    const float* b_c1 = (const float*)d_in[8];
    const float* W_c2 = (const float*)d_in[9];
    const float* b_c2 = (const float*)d_in[10];
    const float* W_lp = (const float*)d_in[11];
    const float* b_lp = (const float*)d_in[12];
    float* out = (float*)d_out;

    float *p_xw, *p_h1, *p_h2, *p_xg, *p_t40;
    cudaGetSymbolAddress((void**)&p_xw,  g_xw);
    cudaGetSymbolAddress((void**)&p_h1,  g_h1);
    cudaGetSymbolAddress((void**)&p_h2,  g_h2);
    cudaGetSymbolAddress((void**)&p_xg,  g_xg);
    cudaGetSymbolAddress((void**)&p_t40, g_t40);

    const int B = 256;
    dim3 g64(64, 4), g40(40, 4);

    k_detect<<<1, 256>>>((const int*)eidx, (const int*)hidx);

    // degrees
    k_zero_deg<<<(NN + B - 1) / B, B>>>();
    k_hdeg<<<(PP + B - 1) / B, B>>>(hidx);
    k_gdeg<<<(EE + B - 1) / B, B>>>(eidx);
    k_fin_dis<<<(NN + B - 1) / B, B>>>();

    // ---- hyperconv 1 ----
    k_gemm<FIN, D><<<(NN + 31) / 32, g64>>>(x, W_h1, p_xw, nullptr);
    k_zero_ef<<<(HEN * D + B - 1) / B, B>>>();
    k_scat_n2e<<<(PP * 16 + B - 1) / B, B>>>(p_xw, hidx);
    k_scale_ef<<<(HEN * D + B - 1) / B, B>>>();
    k_zero_acc64<<<(NN * D + B - 1) / B, B>>>();
    k_scat_e2n<<<(PP * 16 + B - 1) / B, B>>>(hidx);
    k_epi_hyper<<<(NN * D + B - 1) / B, B>>>(b_h1, p_h1, 1);

    // ---- hyperconv 2 ----
    k_gemm<D, D><<<(NN + 31) / 32, g64>>>(p_h1, W_h2, p_xw, nullptr);
    k_zero_ef<<<(HEN * D + B - 1) / B, B>>>();
    k_scat_n2e<<<(PP * 16 + B - 1) / B, B>>>(p_xw, hidx);
    k_scale_ef<<<(HEN * D + B - 1) / B, B>>>();
    k_zero_acc64<<<(NN * D + B - 1) / B, B>>>();
    k_scat_e2n<<<(PP * 16 + B - 1) / B, B>>>(hidx);
    k_epi_hyper<<<(NN * D + B - 1) / B, B>>>(b_h2, p_h2, 0);

    // ---- gcn 1 (concat input) ----
    float* p_dis; cudaGetSymbolAddress((void**)&p_dis, g_dis);
    k_gemm_cat<<<(NN + 31) / 32, g64>>>(x, p_h2, W_c1, p_xw, p_dis);
    k_zero_acc64<<<(NN * D + B - 1) / B, B>>>();
    k_gcn_scat64<<<(EE * 16 + B - 1) / B, B>>>(p_xw, eidx);
    k_epi_gcn<<<(NN * D + B - 1) / B, B>>>(p_xw, b_c1, p_xg);

    // ---- gcn 2 (+ fused linear head) ----
    k_gemm<D, NC><<<(NN + 31) / 32, g40>>>(p_xg, W_c2, p_t40, p_dis);
    k_zero_acc40<<<(NN * NC + B - 1) / B, B>>>();
    k_gcn_scat40<<<(EE + 31) / 32, 320>>>(eidx);
    k_final<<<(NN + 5) / 6, 240>>>(W_lp, b_lp, b_c2, out);
}

// round 2
// speedup vs baseline: 2.7673x; 2.7673x over previous
#include <cuda_runtime.h>

#define NN  100000
#define EE  1600000
#define PP  800000
#define HEN 20000
#define FIN 128
#define D   64
#define NC  40

// ---------------- scratch (device globals; no allocation allowed) ----------------
__device__ float g_xw [NN * D];     // gemm output (xwd); reused as head input [NN,40]
__device__ float g_h1 [NN * D];
__device__ float g_h2 [NN * D];
__device__ float g_xg [NN * D];
__device__ float g_t40[NN * NC];
__device__ float g_ef [HEN * D];
__device__ float g_dis  [NN];       // rsqrt(in-deg + 1)
__device__ float g_Dninv[NN];       // 1/hyper node degree
__device__ float g_Binv [HEN];      // 1/hyperedge size
__device__ int g_cntE[NN], g_cntH[HEN], g_cntN[NN];
__device__ int g_offE[NN + 1], g_offH[HEN + 1], g_offN[NN + 1];
__device__ int g_curE[NN], g_curH[HEN], g_curN[NN];
__device__ int g_csrE[EE];          // dst -> src list
__device__ int g_csrHn[PP];         // he  -> node list
__device__ int g_csrNh[PP];         // node-> he list
__device__ int g_bsum[1024];
__device__ int g_me, g_mh;          // 1 if int64 indices, 0 if int32

// ---------------- helpers ----------------
__device__ __forceinline__ long long ldidx(const void* b, long long i, int m64) {
    return m64 ? ((const long long*)b)[i] : (long long)((const int*)b)[i];
}

// ---------------- dtype detection ----------------
__global__ void k_detect(const int* e32, const int* h32) {
    int nze = 0, nzh = 0;
    for (int i = threadIdx.x; i < 4096; i += blockDim.x) {
        if (e32[2 * i + 1] != 0) nze = 1;
        if (h32[2 * i + 1] != 0) nzh = 1;
    }
    nze = __syncthreads_or(nze);
    nzh = __syncthreads_or(nzh);
    if (threadIdx.x == 0) { g_me = nze ? 0 : 1; g_mh = nzh ? 0 : 1; }
}

// ---------------- counting ----------------
__global__ void k_zero_cnt() {
    int i = blockIdx.x * blockDim.x + threadIdx.x;
    if (i < NN) { g_cntE[i] = 0; g_cntN[i] = 0; }
    if (i < HEN) g_cntH[i] = 0;
}
__global__ void k_cnt_e(const void* eidx) {
    int i = blockIdx.x * blockDim.x + threadIdx.x;
    if (i >= EE) return;
    int dst = (int)ldidx(eidx, (long long)EE + i, g_me);
    atomicAdd(&g_cntE[dst], 1);
}
__global__ void k_cnt_h(const void* hidx) {
    int i = blockIdx.x * blockDim.x + threadIdx.x;
    if (i >= PP) return;
    int m = g_mh;
    int node = (int)ldidx(hidx, i, m);
    int he   = (int)ldidx(hidx, (long long)PP + i, m);
    atomicAdd(&g_cntN[node], 1);
    atomicAdd(&g_cntH[he], 1);
}

// ---------------- exclusive scan (3 kernels, n <= 1024*1024) ----------------
__global__ void k_scan1(const int* cnt, int n, int* excl, int* bsum) {
    __shared__ int wsum[8];
    int t = threadIdx.x;                       // 256 threads, 4 elems each
    int base = blockIdx.x * 1024 + t * 4;
    int v0 = 0, v1 = 0, v2 = 0, v3 = 0;
    if (base + 0 < n) v0 = cnt[base + 0];
    if (base + 1 < n) v1 = cnt[base + 1];
    if (base + 2 < n) v2 = cnt[base + 2];
    if (base + 3 < n) v3 = cnt[base + 3];
    int tot = v0 + v1 + v2 + v3;
    int lane = t & 31, w = t >> 5;
    int p = tot;
    for (int d = 1; d < 32; d <<= 1) { int u = __shfl_up_sync(~0u, p, d); if (lane >= d) p += u; }
    if (lane == 31) wsum[w] = p;
    __syncthreads();
    int wb = 0;
    for (int i = 0; i < w; i++) wb += wsum[i];
    int e0 = wb + p - tot;
    if (base + 0 < n) excl[base + 0] = e0;
    if (base + 1 < n) excl[base + 1] = e0 + v0;
    if (base + 2 < n) excl[base + 2] = e0 + v0 + v1;
    if (base + 3 < n) excl[base + 3] = e0 + v0 + v1 + v2;
    if (t == 255) bsum[blockIdx.x] = wb + p;
}
__global__ void k_scan2(int* b, int nb) {
    int t = threadIdx.x;                       // 1024 threads
    int v = (t < nb) ? b[t] : 0;
    int lane = t & 31, w = t >> 5;
    int p = v;
    for (int d = 1; d < 32; d <<= 1) { int u = __shfl_up_sync(~0u, p, d); if (lane >= d) p += u; }
    __shared__ int ws[32];
    if (lane == 31) ws[w] = p;
    __syncthreads();
    if (t < 32) {
        int q = ws[t], pp = q;
        for (int d = 1; d < 32; d <<= 1) { int u = __shfl_up_sync(~0u, pp, d); if (t >= d) pp += u; }
        ws[t] = pp - q;                        // exclusive warp base
    }
    __syncthreads();
    if (t < nb) b[t] = ws[w] + p - v;
}
__global__ void k_scan3(int* offs, int n, const int* bsum, int* cur, int total) {
    int i = blockIdx.x * blockDim.x + threadIdx.x;
    if (i < n) { int v = offs[i] + bsum[i >> 10]; offs[i] = v; cur[i] = v; }
    if (i == 0) offs[n] = total;
}

// ---------------- norms + CSR fill ----------------
__global__ void k_norms() {
    int i = blockIdx.x * blockDim.x + threadIdx.x;
    if (i < NN) {
        g_dis[i] = rsqrtf((float)g_cntE[i] + 1.0f);
        int dn = g_cntN[i];
        g_Dninv[i] = dn > 0 ? 1.0f / (float)dn : 0.0f;
    }
    if (i < HEN) {
        int bh = g_cntH[i];
        g_Binv[i] = bh > 0 ? 1.0f / (float)bh : 0.0f;
    }
}
__global__ void k_fill_e(const void* eidx) {
    int i = blockIdx.x * blockDim.x + threadIdx.x;
    if (i >= EE) return;
    int m = g_me;
    int src = (int)ldidx(eidx, i, m);
    int dst = (int)ldidx(eidx, (long long)EE + i, m);
    int pos = atomicAdd(&g_curE[dst], 1);
    g_csrE[pos] = src;
}
__global__ void k_fill_h(const void* hidx) {
    int i = blockIdx.x * blockDim.x + threadIdx.x;
    if (i >= PP) return;
    int m = g_mh;
    int node = (int)ldidx(hidx, i, m);
    int he   = (int)ldidx(hidx, (long long)PP + i, m);
    int p1 = atomicAdd(&g_curH[he], 1);   g_csrHn[p1] = node;
    int p2 = atomicAdd(&g_curN[node], 1); g_csrNh[p2] = he;
}

// ---------------- register-tiled GEMM: out = rowscale * ([A1|A2] @ W) + bias ----------------
template<int K1, int K2, int C>
__global__ void k_gemm(const float* __restrict__ A1, const float* __restrict__ A2,
                       const float* __restrict__ W, float* __restrict__ out,
                       const float* __restrict__ rowscale, const float* __restrict__ bias) {
    constexpr int KT = K1 + K2;
    constexpr int CG = C / 4;
    __shared__ float Ws[KT * C];
    int tid = threadIdx.x;                     // CG*16 threads
    for (int i = tid; i < KT * C; i += CG * 16) Ws[i] = W[i];
    __syncthreads();
    int cg = tid % CG, rg = tid / CG;
    int row0 = blockIdx.x * 64 + rg * 4;
    int r[4];
    #pragma unroll
    for (int j = 0; j < 4; j++) { int rr = row0 + j; r[j] = rr < NN ? rr : NN - 1; }

    float acc[4][4] = {};
    #pragma unroll 2
    for (int k = 0; k < K1; k += 4) {
        float a[4][4];
        #pragma unroll
        for (int j = 0; j < 4; j++)
            *(float4*)a[j] = *(const float4*)(A1 + (size_t)r[j] * K1 + k);
        #pragma unroll
        for (int kk = 0; kk < 4; kk++) {
            float w[4];
            *(float4*)w = *(const float4*)&Ws[(k + kk) * C + cg * 4];
            #pragma unroll
            for (int j = 0; j < 4; j++)
                #pragma unroll
                for (int c = 0; c < 4; c++)
                    acc[j][c] = fmaf(a[j][kk], w[c], acc[j][c]);
        }
    }
    if (K2 > 0) {
        #pragma unroll 2
        for (int k = 0; k < K2; k += 4) {
            float a[4][4];
            #pragma unroll
            for (int j = 0; j < 4; j++)
                *(float4*)a[j] = *(const float4*)(A2 + (size_t)r[j] * K2 + k);
            #pragma unroll
            for (int kk = 0; kk < 4; kk++) {
                float w[4];
                *(float4*)w = *(const float4*)&Ws[(K1 + k + kk) * C + cg * 4];
                #pragma unroll
                for (int j = 0; j < 4; j++)
                    #pragma unroll
                    for (int c = 0; c < 4; c++)
                        acc[j][c] = fmaf(a[j][kk], w[c], acc[j][c]);
            }
        }
    }
    #pragma unroll
    for (int j = 0; j < 4; j++) {
        int rr = row0 + j;
        if (rr >= NN) break;
        float s = rowscale ? rowscale[rr] : 1.0f;
        float4 o;
        o.x = acc[j][0] * s; o.y = acc[j][1] * s; o.z = acc[j][2] * s; o.w = acc[j][3] * s;
        if (bias) {
            const float4 bb = *(const float4*)(bias + cg * 4);
            o.x += bb.x; o.y += bb.y; o.z += bb.z; o.w += bb.w;
        }
        *(float4*)(out + (size_t)rr * C + cg * 4) = o;
    }
}

// ---------------- gathers (CSR, register accumulate, fused epilogues) ----------------
__global__ void k_gath_he(const float* __restrict__ xw) {
    int t = blockIdx.x * blockDim.x + threadIdx.x;
    int he = t >> 4, l = t & 15;
    if (he >= HEN) return;
    int s = g_offH[he], e = g_offH[he + 1];
    float4 acc = make_float4(0.f, 0.f, 0.f, 0.f);
    int i = s;
    for (; i + 1 < e; i += 2) {
        int n0 = g_csrHn[i], n1 = g_csrHn[i + 1];
        float4 v0 = *(const float4*)(xw + (size_t)n0 * D + l * 4);
        float4 v1 = *(const float4*)(xw + (size_t)n1 * D + l * 4);
        acc.x += v0.x + v1.x; acc.y += v0.y + v1.y;
        acc.z += v0.z + v1.z; acc.w += v0.w + v1.w;
    }
    if (i < e) {
        int n0 = g_csrHn[i];
        float4 v0 = *(const float4*)(xw + (size_t)n0 * D + l * 4);
        acc.x += v0.x; acc.y += v0.y; acc.z += v0.z; acc.w += v0.w;
    }
    float b = g_Binv[he];
    acc.x *= b; acc.y *= b; acc.z *= b; acc.w *= b;
    *(float4*)(g_ef + (size_t)he * D + l * 4) = acc;
}

__global__ void k_gath_e2n(const float* __restrict__ bias, float* __restrict__ out, int relu) {
    int t = blockIdx.x * blockDim.x + threadIdx.x;
    int node = t >> 4, l = t & 15;
    if (node >= NN) return;
    int s = g_offN[node], e = g_offN[node + 1];
    float4 acc = make_float4(0.f, 0.f, 0.f, 0.f);
    int i = s;
    for (; i + 1 < e; i += 2) {
        int h0 = g_csrNh[i], h1 = g_csrNh[i + 1];
        float4 v0 = *(const float4*)(g_ef + (size_t)h0 * D + l * 4);
        float4 v1 = *(const float4*)(g_ef + (size_t)h1 * D + l * 4);
        acc.x += v0.x + v1.x; acc.y += v0.y + v1.y;
        acc.z += v0.z + v1.z; acc.w += v0.w + v1.w;
    }
    if (i < e) {
        int h0 = g_csrNh[i];
        float4 v0 = *(const float4*)(g_ef + (size_t)h0 * D + l * 4);
        acc.x += v0.x; acc.y += v0.y; acc.z += v0.z; acc.w += v0.w;
    }
    float dv = g_Dninv[node];
    float4 bb = *(const float4*)(bias + l * 4);
    float4 o;
    o.x = dv * acc.x + bb.x; o.y = dv * acc.y + bb.y;
    o.z = dv * acc.z + bb.z; o.w = dv * acc.w + bb.w;
    if (relu) {
        o.x = fmaxf(o.x, 0.f); o.y = fmaxf(o.y, 0.f);
        o.z = fmaxf(o.z, 0.f); o.w = fmaxf(o.w, 0.f);
    }
    *(float4*)(out + (size_t)node * D + l * 4) = o;
}

__global__ void k_gcn64(const float* __restrict__ xwd, const float* __restrict__ bias,
                        float* __restrict__ out) {
    int t = blockIdx.x * blockDim.x + threadIdx.x;
    int node = t >> 4, l = t & 15;
    if (node >= NN) return;
    int s = g_offE[node], e = g_offE[node + 1];
    float4 acc = make_float4(0.f, 0.f, 0.f, 0.f);
    int i = s;
    for (; i + 1 < e; i += 2) {
        int s0 = g_csrE[i], s1 = g_csrE[i + 1];
        float4 v0 = *(const float4*)(xwd + (size_t)s0 * D + l * 4);
        float4 v1 = *(const float4*)(xwd + (size_t)s1 * D + l * 4);
        acc.x += v0.x + v1.x; acc.y += v0.y + v1.y;
        acc.z += v0.z + v1.z; acc.w += v0.w + v1.w;
    }
    if (i < e) {
        int s0 = g_csrE[i];
        float4 v0 = *(const float4*)(xwd + (size_t)s0 * D + l * 4);
        acc.x += v0.x; acc.y += v0.y; acc.z += v0.z; acc.w += v0.w;
    }
    float4 self = *(const float4*)(xwd + (size_t)node * D + l * 4);
    float ds = g_dis[node];
    float4 bb = *(const float4*)(bias + l * 4);
    float4 o;
    o.x = fmaxf(ds * (acc.x + self.x) + bb.x, 0.f);
    o.y = fmaxf(ds * (acc.y + self.y) + bb.y, 0.f);
    o.z = fmaxf(ds * (acc.z + self.z) + bb.z, 0.f);
    o.w = fmaxf(ds * (acc.w + self.w) + bb.w, 0.f);
    *(float4*)(out + (size_t)node * D + l * 4) = o;
}

__global__ void k_gcn40(const float* __restrict__ bias, float* __restrict__ out) {
    int t = blockIdx.x * blockDim.x + threadIdx.x;   // 320 threads = 32 nodes
    int node = t / 10, l = t % 10;
    if (node >= NN) return;
    int s = g_offE[node], e = g_offE[node + 1];
    float4 acc = make_float4(0.f, 0.f, 0.f, 0.f);
    int i = s;
    for (; i + 1 < e; i += 2) {
        int s0 = g_csrE[i], s1 = g_csrE[i + 1];
        float4 v0 = *(const float4*)(g_t40 + (size_t)s0 * NC + l * 4);
        float4 v1 = *(const float4*)(g_t40 + (size_t)s1 * NC + l * 4);
        acc.x += v0.x + v1.x; acc.y += v0.y + v1.y;
        acc.z += v0.z + v1.z; acc.w += v0.w + v1.w;
    }
    if (i < e) {
        int s0 = g_csrE[i];
        float4 v0 = *(const float4*)(g_t40 + (size_t)s0 * NC + l * 4);
        acc.x += v0.x; acc.y += v0.y; acc.z += v0.z; acc.w += v0.w;
    }
    float4 self = *(const float4*)(g_t40 + (size_t)node * NC + l * 4);
    float ds = g_dis[node];
    float4 bb = *(const float4*)(bias + l * 4);
    float4 o;
    o.x = ds * (acc.x + self.x) + bb.x;
    o.y = ds * (acc.y + self.y) + bb.y;
    o.z = ds * (acc.z + self.z) + bb.z;
    o.w = ds * (acc.w + self.w) + bb.w;
    *(float4*)(out + (size_t)node * NC + l * 4) = o;   // h before final linear
}

// ---------------- launch ----------------
extern "C" void kernel_launch(void* const* d_in, const int* in_sizes, int n_in,
                              void* d_out, int out_size) {
    const float* x    = (const float*)d_in[0];
    const void*  eidx = d_in[1];
    const void*  hidx = d_in[2];
    const float* W_h1 = (const float*)d_in[3];
    const float* b_h1 = (const float*)d_in[4];
    const float* W_h2 = (const float*)d_in[5];
    const float* b_h2 = (const float*)d_in[6];
    const float* W_c1 = (const float*)d_in[7];
    const float* b_c1 = (const float*)d_in[8];
    const float* W_c2 = (const float*)d_in[9];
    const float* b_c2 = (const float*)d_in[10];
    const float* W_lp = (const float*)d_in[11];
    const float* b_lp = (const float*)d_in[12];
    float* out = (float*)d_out;

    float *p_xw, *p_h1, *p_h2, *p_xg, *p_t40, *p_dis;
    cudaGetSymbolAddress((void**)&p_xw,  g_xw);
    cudaGetSymbolAddress((void**)&p_h1,  g_h1);
    cudaGetSymbolAddress((void**)&p_h2,  g_h2);
    cudaGetSymbolAddress((void**)&p_xg,  g_xg);
    cudaGetSymbolAddress((void**)&p_t40, g_t40);
    cudaGetSymbolAddress((void**)&p_dis, g_dis);
    int *p_cntE, *p_cntH, *p_cntN, *p_offE, *p_offH, *p_offN, *p_curE, *p_curH, *p_curN, *p_bsum;
    cudaGetSymbolAddress((void**)&p_cntE, g_cntE);
    cudaGetSymbolAddress((void**)&p_cntH, g_cntH);
    cudaGetSymbolAddress((void**)&p_cntN, g_cntN);
    cudaGetSymbolAddress((void**)&p_offE, g_offE);
    cudaGetSymbolAddress((void**)&p_offH, g_offH);
    cudaGetSymbolAddress((void**)&p_offN, g_offN);
    cudaGetSymbolAddress((void**)&p_curE, g_curE);
    cudaGetSymbolAddress((void**)&p_curH, g_curH);
    cudaGetSymbolAddress((void**)&p_curN, g_curN);
    cudaGetSymbolAddress((void**)&p_bsum, g_bsum);

    const int B = 256;

    k_detect<<<1, 256>>>((const int*)eidx, (const int*)hidx);

    // ---- CSR build ----
    k_zero_cnt<<<(NN + B - 1) / B, B>>>();
    k_cnt_e<<<(EE + B - 1) / B, B>>>(eidx);
    k_cnt_h<<<(PP + B - 1) / B, B>>>(hidx);

    k_scan1<<<(NN + 1023) / 1024, 256>>>(p_cntE, NN, p_offE, p_bsum);
    k_scan2<<<1, 1024>>>(p_bsum, (NN + 1023) / 1024);
    k_scan3<<<(NN + B - 1) / B, B>>>(p_offE, NN, p_bsum, p_curE, EE);

    k_scan1<<<(HEN + 1023) / 1024, 256>>>(p_cntH, HEN, p_offH, p_bsum);
    k_scan2<<<1, 1024>>>(p_bsum, (HEN + 1023) / 1024);
    k_scan3<<<(HEN + B - 1) / B, B>>>(p_offH, HEN, p_bsum, p_curH, PP);

    k_scan1<<<(NN + 1023) / 1024, 256>>>(p_cntN, NN, p_offN, p_bsum);
    k_scan2<<<1, 1024>>>(p_bsum, (NN + 1023) / 1024);
    k_scan3<<<(NN + B - 1) / B, B>>>(p_offN, NN, p_bsum, p_curN, PP);

    k_norms<<<(NN + B - 1) / B, B>>>();
    k_fill_e<<<(EE + B - 1) / B, B>>>(eidx);
    k_fill_h<<<(PP + B - 1) / B, B>>>(hidx);

    const int GR = (NN + 63) / 64;   // gemm grid (64 rows/block)

    // ---- hyperconv 1 ----
    k_gemm<FIN, 0, D><<<GR, 256>>>(x, nullptr, W_h1, p_xw, nullptr, nullptr);
    k_gath_he<<<(HEN * 16 + B - 1) / B, B>>>(p_xw);
    k_gath_e2n<<<(NN * 16 + B - 1) / B, B>>>(b_h1, p_h1, 1);

    // ---- hyperconv 2 ----
    k_gemm<D, 0, D><<<GR, 256>>>(p_h1, nullptr, W_h2, p_xw, nullptr, nullptr);
    k_gath_he<<<(HEN * 16 + B - 1) / B, B>>>(p_xw);
    k_gath_e2n<<<(NN * 16 + B - 1) / B, B>>>(b_h2, p_h2, 0);

    // ---- gcn 1 (concat input, dis-prescaled) ----
    k_gemm<FIN, D, D><<<GR, 256>>>(x, p_h2, W_c1, p_xw, p_dis, nullptr);
    k_gcn64<<<(NN * 16 + B - 1) / B, B>>>(p_xw, b_c1, p_xg);

    // ---- gcn 2 + linear head ----
    k_gemm<D, 0, NC><<<GR, 160>>>(p_xg, nullptr, W_c2, p_t40, p_dis, nullptr);
    k_gcn40<<<(NN * 10 + 319) / 320, 320>>>(b_c2, p_xw);
    k_gemm<NC, 0, NC><<<GR, 160>>>(p_xw, nullptr, W_lp, out, nullptr, b_lp);
}